// round 1
// baseline (speedup 1.0000x reference)
#include <cuda_runtime.h>
#include <cuda_bf16.h>

// Problem constants
#define Hd   256
#define Ld   512
#define Bq   8
#define NTOK 4096            // B*L
#define Vv   32000
#define CEMA 0.05f           // 1 - alpha

// Scratch (device globals: no allocation allowed)
__device__ float g_t1[NTOK * 512];   // relu(h@W1+b1)   [4096,512]
__device__ float g_x [NTOK * Hd];    // h + ff          [4096,256]
__device__ float g_he[NTOK * Hd];    // LayerNorm out   [4096,256]
__device__ float g_in[NTOK];         // 1/max(||he||,1e-12) per row
__device__ float g_m [Bq * Hd];      // readout m
__device__ float g_mm[Bq * Hd];      // m@Wrp + brp

// ---------------------------------------------------------------------------
// Tiled SGEMM: C[M,N] = op(A @ B + bias)
//   GATHER: A[row][k] = embed[seq[row]*K + k]
//   RELU:   relu epilogue
//   RESID:  C += embed[seq[row]*N + col]   (residual for GEMM2, N==Hd)
// BM=64, BN=64, BK=16, 256 threads, 4x4 microtile
// ---------------------------------------------------------------------------
template<bool GATHER, bool RELU, bool RESID>
__global__ __launch_bounds__(256) void sgemm_kernel(
    const float* __restrict__ A, const float* __restrict__ Bm,
    const float* __restrict__ bias, float* __restrict__ C,
    int M, int N, int K,
    const int* __restrict__ seq, const float* __restrict__ embed)
{
    constexpr int BM = 64, BN = 64, BK = 16, TM = 4, TN = 4;
    __shared__ float As[BK][BM];
    __shared__ float Bs[BK][BN];

    const int tid = threadIdx.x;
    const int tx = tid % (BN / TN);   // 0..15
    const int ty = tid / (BN / TN);   // 0..15
    const int rowBase = blockIdx.y * BM;
    const int colBase = blockIdx.x * BN;

    float acc[TM][TN];
    #pragma unroll
    for (int i = 0; i < TM; i++)
        #pragma unroll
        for (int j = 0; j < TN; j++) acc[i][j] = 0.f;

    for (int k0 = 0; k0 < K; k0 += BK) {
        // load A tile (BM x BK) -> As[k][m]
        #pragma unroll
        for (int i = tid; i < BM * BK; i += 256) {
            int m = i / BK, kk = i % BK;
            int gr = rowBase + m;
            const float* arow = GATHER ? (embed + (long)seq[gr] * K)
                                       : (A + (long)gr * K);
            As[kk][m] = arow[k0 + kk];
        }
        // load B tile (BK x BN)
        #pragma unroll
        for (int i = tid; i < BK * BN; i += 256) {
            int kk = i / BN, n = i % BN;
            Bs[kk][n] = Bm[(long)(k0 + kk) * N + colBase + n];
        }
        __syncthreads();

        #pragma unroll
        for (int kk = 0; kk < BK; kk++) {
            float af[TM], bf[TN];
            #pragma unroll
            for (int i = 0; i < TM; i++) af[i] = As[kk][ty * TM + i];
            #pragma unroll
            for (int j = 0; j < TN; j++) bf[j] = Bs[kk][tx * TN + j];
            #pragma unroll
            for (int i = 0; i < TM; i++)
                #pragma unroll
                for (int j = 0; j < TN; j++) acc[i][j] += af[i] * bf[j];
        }
        __syncthreads();
    }

    #pragma unroll
    for (int i = 0; i < TM; i++) {
        int r = rowBase + ty * TM + i;
        const float* erow = RESID ? (embed + (long)seq[r] * N) : nullptr;
        #pragma unroll
        for (int j = 0; j < TN; j++) {
            int c = colBase + tx * TN + j;
            float v = acc[i][j] + bias[c];
            if (RELU)  v = fmaxf(v, 0.f);
            if (RESID) v += erow[c];
            C[(long)r * N + c] = v;
        }
    }
}

// ---------------------------------------------------------------------------
// LayerNorm + row-norm: one warp per row (8 rows / 256-thread block)
// ---------------------------------------------------------------------------
__global__ __launch_bounds__(256) void ln_kernel(
    const float* __restrict__ X, const float* __restrict__ g,
    const float* __restrict__ b, float* __restrict__ Y,
    float* __restrict__ invn)
{
    int row  = blockIdx.x * 8 + (threadIdx.x >> 5);
    int lane = threadIdx.x & 31;
    const float* x = X + (long)row * Hd;

    float v[8];
    float s = 0.f;
    #pragma unroll
    for (int j = 0; j < 8; j++) { v[j] = x[lane + 32 * j]; s += v[j]; }
    #pragma unroll
    for (int o = 16; o > 0; o >>= 1) s += __shfl_xor_sync(0xffffffff, s, o);
    float mu = s * (1.f / Hd);

    float ss = 0.f;
    #pragma unroll
    for (int j = 0; j < 8; j++) { float d = v[j] - mu; ss += d * d; }
    #pragma unroll
    for (int o = 16; o > 0; o >>= 1) ss += __shfl_xor_sync(0xffffffff, ss, o);
    float rstd = rsqrtf(ss * (1.f / Hd) + 1e-5f);

    float ns = 0.f;
    #pragma unroll
    for (int j = 0; j < 8; j++) {
        int c = lane + 32 * j;
        float o = (v[j] - mu) * rstd * g[c] + b[c];
        Y[(long)row * Hd + c] = o;
        ns += o * o;
    }
    #pragma unroll
    for (int o = 16; o > 0; o >>= 1) ns += __shfl_xor_sync(0xffffffff, ns, o);

    if (lane == 0) invn[row] = 1.f / fmaxf(sqrtf(ns), 1e-12f);
}

// ---------------------------------------------------------------------------
// Backward delta-rule scan (the math reformulation):
//   v_{T+1} = q;  for t = T..1:  s = kn_t . v;  m += c*s*k_t;  v -= c*s*kn_t
// One warp per batch, v and m register-resident, 2-deep key prefetch.
// Keys: rows b*512 + t, t = 0..510.  q: row b*512 + 511.
// ---------------------------------------------------------------------------
__global__ __launch_bounds__(32) void scan_kernel(
    const float* __restrict__ He, const float* __restrict__ invn,
    float* __restrict__ mout)
{
    int b = blockIdx.x;
    int lane = threadIdx.x;
    const float* Hb = He + (long)b * Ld * Hd;
    const float* In = invn + (long)b * Ld;

    float v[8], m[8];
    #pragma unroll
    for (int j = 0; j < 8; j++) {
        v[j] = Hb[511 * Hd + lane + 32 * j];
        m[j] = 0.f;
    }

    float kc[8], kn[8], ic, inx;
    #pragma unroll
    for (int j = 0; j < 8; j++) kc[j] = Hb[510 * Hd + lane + 32 * j];
    ic = In[510];
    #pragma unroll
    for (int j = 0; j < 8; j++) kn[j] = Hb[509 * Hd + lane + 32 * j];
    inx = In[509];

    #pragma unroll 1
    for (int t = 510; t >= 0; --t) {
        // prefetch t-2 (2-deep pipeline covers L2 latency)
        float pk[8], pi = 0.f;
        if (t >= 2) {
            const float* r = Hb + (long)(t - 2) * Hd + lane;
            #pragma unroll
            for (int j = 0; j < 8; j++) pk[j] = r[32 * j];
            pi = In[t - 2];
        }

        // dot(k_t, v) with balanced tree
        float p0 = kc[0] * v[0] + kc[1] * v[1];
        float p1 = kc[2] * v[2] + kc[3] * v[3];
        float p2 = kc[4] * v[4] + kc[5] * v[5];
        float p3 = kc[6] * v[6] + kc[7] * v[7];
        float p = (p0 + p1) + (p2 + p3);
        #pragma unroll
        for (int o = 16; o > 0; o >>= 1) p += __shfl_xor_sync(0xffffffff, p, o);

        float s   = p * ic;          // kn . v
        float cs  = CEMA * s;
        float csn = cs * ic;
        #pragma unroll
        for (int j = 0; j < 8; j++) {
            m[j] += cs * kc[j];      // m += c*s*k
            v[j] -= csn * kc[j];     // v -= c*s*kn
        }

        // rotate pipeline
        #pragma unroll
        for (int j = 0; j < 8; j++) { kc[j] = kn[j]; kn[j] = pk[j]; }
        ic = inx; inx = pi;
    }

    #pragma unroll
    for (int j = 0; j < 8; j++)
        mout[b * Hd + lane + 32 * j] = m[j];
}

// ---------------------------------------------------------------------------
// mm = m @ Wrp + brp   (tiny: 8x256)
// ---------------------------------------------------------------------------
__global__ __launch_bounds__(256) void rp_kernel(
    const float* __restrict__ m, const float* __restrict__ Wrp,
    const float* __restrict__ brp, float* __restrict__ mm)
{
    int b = blockIdx.x, c = threadIdx.x;
    __shared__ float ms[Hd];
    ms[c] = m[b * Hd + c];
    __syncthreads();
    float acc = brp[c];
    #pragma unroll 8
    for (int k = 0; k < Hd; k++) acc += ms[k] * Wrp[k * Hd + c];
    mm[b * Hd + c] = acc;
}

// ---------------------------------------------------------------------------
// out[8,32000] = mm @ Wout + bout   (memory-bound on Wout)
// ---------------------------------------------------------------------------
__global__ __launch_bounds__(128) void out_kernel(
    const float* __restrict__ mm, const float* __restrict__ Wout,
    const float* __restrict__ bout, float* __restrict__ out)
{
    __shared__ float ms[Bq][Hd];
    int tid = threadIdx.x;
    #pragma unroll
    for (int i = tid; i < Bq * Hd; i += 128) ms[i >> 8][i & 255] = mm[i];
    __syncthreads();

    int col = blockIdx.x * 128 + tid;
    float acc[Bq];
    float bo = bout[col];
    #pragma unroll
    for (int b = 0; b < Bq; b++) acc[b] = bo;

    #pragma unroll 4
    for (int k = 0; k < Hd; k++) {
        float w = Wout[(long)k * Vv + col];
        #pragma unroll
        for (int b = 0; b < Bq; b++) acc[b] += ms[b][k] * w;
    }
    #pragma unroll
    for (int b = 0; b < Bq; b++) out[(long)b * Vv + col] = acc[b];
}

// ---------------------------------------------------------------------------
extern "C" void kernel_launch(void* const* d_in, const int* in_sizes, int n_in,
                              void* d_out, int out_size)
{
    const int*   seq   = (const int*)  d_in[0];
    const float* embed = (const float*)d_in[1];
    const float* W1    = (const float*)d_in[2];
    const float* b1    = (const float*)d_in[3];
    const float* W2    = (const float*)d_in[4];
    const float* b2    = (const float*)d_in[5];
    const float* gamma = (const float*)d_in[6];
    const float* beta  = (const float*)d_in[7];
    const float* Wrp   = (const float*)d_in[8];
    const float* brp   = (const float*)d_in[9];
    const float* Wout  = (const float*)d_in[10];
    const float* bout  = (const float*)d_in[11];
    float* out = (float*)d_out;

    float *t1, *x, *he, *invn, *m, *mm;
    cudaGetSymbolAddress((void**)&t1,   g_t1);
    cudaGetSymbolAddress((void**)&x,    g_x);
    cudaGetSymbolAddress((void**)&he,   g_he);
    cudaGetSymbolAddress((void**)&invn, g_in);
    cudaGetSymbolAddress((void**)&m,    g_m);
    cudaGetSymbolAddress((void**)&mm,   g_mm);

    // 1) t1 = relu(embed[seq] @ W1 + b1)   [4096,512], K=256
    sgemm_kernel<true, true, false><<<dim3(512 / 64, 4096 / 64), 256>>>(
        nullptr, W1, b1, t1, NTOK, 512, Hd, seq, embed);

    // 2) x = t1 @ W2 + b2 + embed[seq]     [4096,256], K=512
    sgemm_kernel<false, false, true><<<dim3(Hd / 64, 4096 / 64), 256>>>(
        t1, W2, b2, x, NTOK, Hd, 512, seq, embed);

    // 3) he = LN(x)*gamma+beta; invn = 1/max(||he||,1e-12)
    ln_kernel<<<NTOK / 8, 256>>>(x, gamma, beta, he, invn);

    // 4) backward delta-rule scan -> m[8,256]
    scan_kernel<<<Bq, 32>>>(he, invn, m);

    // 5) mm = m @ Wrp + brp
    rp_kernel<<<Bq, Hd>>>(m, Wrp, brp, mm);

    // 6) out = mm @ Wout + bout
    out_kernel<<<Vv / 128, 128>>>(mm, Wout, bout, out);
}

// round 2
// speedup vs baseline: 1.3369x; 1.3369x over previous
#include <cuda_runtime.h>
#include <cuda_bf16.h>

// Problem constants
#define Hd   256
#define Ld   512
#define Bq   8
#define NTOK 4096            // B*L
#define Vv   32000
#define CEMA 0.05f           // 1 - alpha
#define NCH  16              // chunks per batch
#define CSZ  32              // chunk size

// Scratch (device globals: no allocation allowed)
__device__ float g_t1[NTOK * 512];          // relu(h@W1+b1)
__device__ float g_x [NTOK * Hd];           // h + ff
__device__ float g_he[NTOK * Hd];           // LayerNorm out
__device__ float g_in[NTOK];                // 1/max(||he||,1e-12)
__device__ float g_A [Bq * NCH * CSZ * CSZ];// scaled Gram per chunk
__device__ float g_m [Bq * Hd];
__device__ float g_mm[Bq * Hd];

// ---------------------------------------------------------------------------
// Tiled SGEMM (unchanged from R1)
// ---------------------------------------------------------------------------
template<bool GATHER, bool RELU, bool RESID>
__global__ __launch_bounds__(256) void sgemm_kernel(
    const float* __restrict__ A, const float* __restrict__ Bm,
    const float* __restrict__ bias, float* __restrict__ C,
    int M, int N, int K,
    const int* __restrict__ seq, const float* __restrict__ embed)
{
    constexpr int BM = 64, BN = 64, BK = 16, TM = 4, TN = 4;
    __shared__ float As[BK][BM];
    __shared__ float Bs[BK][BN];

    const int tid = threadIdx.x;
    const int tx = tid % (BN / TN);
    const int ty = tid / (BN / TN);
    const int rowBase = blockIdx.y * BM;
    const int colBase = blockIdx.x * BN;

    float acc[TM][TN];
    #pragma unroll
    for (int i = 0; i < TM; i++)
        #pragma unroll
        for (int j = 0; j < TN; j++) acc[i][j] = 0.f;

    for (int k0 = 0; k0 < K; k0 += BK) {
        #pragma unroll
        for (int i = tid; i < BM * BK; i += 256) {
            int m = i / BK, kk = i % BK;
            int gr = rowBase + m;
            const float* arow = GATHER ? (embed + (long)seq[gr] * K)
                                       : (A + (long)gr * K);
            As[kk][m] = arow[k0 + kk];
        }
        #pragma unroll
        for (int i = tid; i < BK * BN; i += 256) {
            int kk = i / BN, n = i % BN;
            Bs[kk][n] = Bm[(long)(k0 + kk) * N + colBase + n];
        }
        __syncthreads();

        #pragma unroll
        for (int kk = 0; kk < BK; kk++) {
            float af[TM], bf[TN];
            #pragma unroll
            for (int i = 0; i < TM; i++) af[i] = As[kk][ty * TM + i];
            #pragma unroll
            for (int j = 0; j < TN; j++) bf[j] = Bs[kk][tx * TN + j];
            #pragma unroll
            for (int i = 0; i < TM; i++)
                #pragma unroll
                for (int j = 0; j < TN; j++) acc[i][j] += af[i] * bf[j];
        }
        __syncthreads();
    }

    #pragma unroll
    for (int i = 0; i < TM; i++) {
        int r = rowBase + ty * TM + i;
        const float* erow = RESID ? (embed + (long)seq[r] * N) : nullptr;
        #pragma unroll
        for (int j = 0; j < TN; j++) {
            int c = colBase + tx * TN + j;
            float v = acc[i][j] + bias[c];
            if (RELU)  v = fmaxf(v, 0.f);
            if (RESID) v += erow[c];
            C[(long)r * N + c] = v;
        }
    }
}

// ---------------------------------------------------------------------------
// LayerNorm + row norm (unchanged)
// ---------------------------------------------------------------------------
__global__ __launch_bounds__(256) void ln_kernel(
    const float* __restrict__ X, const float* __restrict__ g,
    const float* __restrict__ b, float* __restrict__ Y,
    float* __restrict__ invn)
{
    int row  = blockIdx.x * 8 + (threadIdx.x >> 5);
    int lane = threadIdx.x & 31;
    const float* x = X + (long)row * Hd;

    float v[8];
    float s = 0.f;
    #pragma unroll
    for (int j = 0; j < 8; j++) { v[j] = x[lane + 32 * j]; s += v[j]; }
    #pragma unroll
    for (int o = 16; o > 0; o >>= 1) s += __shfl_xor_sync(0xffffffff, s, o);
    float mu = s * (1.f / Hd);

    float ss = 0.f;
    #pragma unroll
    for (int j = 0; j < 8; j++) { float d = v[j] - mu; ss += d * d; }
    #pragma unroll
    for (int o = 16; o > 0; o >>= 1) ss += __shfl_xor_sync(0xffffffff, ss, o);
    float rstd = rsqrtf(ss * (1.f / Hd) + 1e-5f);

    float ns = 0.f;
    #pragma unroll
    for (int j = 0; j < 8; j++) {
        int c = lane + 32 * j;
        float o = (v[j] - mu) * rstd * g[c] + b[c];
        Y[(long)row * Hd + c] = o;
        ns += o * o;
    }
    #pragma unroll
    for (int o = 16; o > 0; o >>= 1) ns += __shfl_xor_sync(0xffffffff, ns, o);

    if (lane == 0) invn[row] = 1.f / fmaxf(sqrtf(ns), 1e-12f);
}

// ---------------------------------------------------------------------------
// Gram kernel: A[b][g][j][l] = CEMA * invn_j*invn_l * (k_{t_j} . k_{t_l})
// Chunk g covers keys t in [32g, min(32g+32, 511)); within a chunk, row j
// maps to t = t_hi - j (descending-time processing order).
// 128 blocks (8 batches x 16 chunks), 256 threads, 4 kk-groups of 64.
// ---------------------------------------------------------------------------
__global__ __launch_bounds__(256) void gram_kernel(
    const float* __restrict__ He, const float* __restrict__ invn,
    float* __restrict__ A)
{
    extern __shared__ float sh[];
    float* Ks   = sh;                 // [32][257]
    float* part = Ks + 32 * 257;      // [4][32][32]
    float* iv   = part + 4 * 1024;    // [32]

    int bId = blockIdx.x >> 4;
    int g   = blockIdx.x & 15;
    int tid = threadIdx.x;
    int tHi = min(32 * g + 31, 510);
    const float* Hb = He + (long)bId * Ld * Hd;

    for (int idx = tid; idx < 32 * 256; idx += 256) {
        int j = idx >> 8, c = idx & 255;
        Ks[j * 257 + c] = Hb[(long)(tHi - j) * Hd + c];
    }
    if (tid < 32) iv[tid] = invn[bId * Ld + tHi - tid];
    __syncthreads();

    int grp = tid >> 6;          // kk partition
    int t64 = tid & 63;
    int tx  = t64 & 7, ty = t64 >> 3;
    int k0  = grp * 64;

    float acc[4][4];
    #pragma unroll
    for (int i = 0; i < 4; i++)
        #pragma unroll
        for (int j = 0; j < 4; j++) acc[i][j] = 0.f;

    #pragma unroll 4
    for (int kk = 0; kk < 64; kk++) {
        float av[4], bv[4];
        #pragma unroll
        for (int i = 0; i < 4; i++) av[i] = Ks[(ty * 4 + i) * 257 + k0 + kk];
        #pragma unroll
        for (int i = 0; i < 4; i++) bv[i] = Ks[(tx * 4 + i) * 257 + k0 + kk];
        #pragma unroll
        for (int i = 0; i < 4; i++)
            #pragma unroll
            for (int j = 0; j < 4; j++) acc[i][j] += av[i] * bv[j];
    }

    #pragma unroll
    for (int i = 0; i < 4; i++)
        #pragma unroll
        for (int j = 0; j < 4; j++)
            part[grp * 1024 + (ty * 4 + i) * 32 + tx * 4 + j] = acc[i][j];
    __syncthreads();

    float* Ab = A + ((long)(bId * NCH + g) << 10);
    for (int e = tid; e < 1024; e += 256) {
        int j = e >> 5, l = e & 31;
        float s = part[e] + part[1024 + e] + part[2048 + e] + part[3072 + e];
        Ab[e] = CEMA * iv[j] * iv[l] * s;
    }
}

// ---------------------------------------------------------------------------
// Chunked backward delta-rule scan. One block per batch, 256 threads.
// Per chunk: b_j = kn_j.v (8 warps), 32-step triangular solve (warp 0,
// while warps 1-7 prefetch next chunk), rank-32 update of v and m (all).
// ---------------------------------------------------------------------------
__global__ __launch_bounds__(256) void scan_kernel(
    const float* __restrict__ He, const float* __restrict__ invn,
    const float* __restrict__ A, float* __restrict__ mout)
{
    extern __shared__ float sh[];
    float* Kb   = sh;                     // [2][32][260]
    float* Asm  = Kb + 2 * 32 * 260;      // [2][32][33]
    float* vsm  = Asm + 2 * 32 * 33;      // [256]
    float* bsm  = vsm + 256;              // [32]
    float* csm  = bsm + 32;               // [32]  c*s_j
    float* cnsm = csm + 32;               // [32]  c*s_j*invn_j
    float* ivs  = cnsm + 32;              // [2][32]

    int bId = blockIdx.x;
    int tid = threadIdx.x;
    int w   = tid >> 5, lane = tid & 31;
    const float* Hb = He + (long)bId * Ld * Hd;
    const float* In = invn + bId * Ld;
    const float* Ab = A + (long)bId * NCH * 1024;

    // prologue: load chunk 15 (t_hi = 510)
    for (int idx = tid; idx < 32 * 64; idx += 256) {
        int j = idx >> 6, c4 = idx & 63;
        float4 v = *(const float4*)(Hb + (long)(510 - j) * Hd + c4 * 4);
        *(float4*)(Kb + j * 260 + c4 * 4) = v;
    }
    for (int idx = tid; idx < 1024; idx += 256)
        Asm[(idx >> 5) * 33 + (idx & 31)] = Ab[15 * 1024 + idx];
    if (tid < 32) ivs[tid] = In[510 - tid];
    vsm[tid] = Hb[511 * Hd + tid];          // v = q
    float mi = 0.f;
    __syncthreads();

    int buf = 0;
    for (int g = 15; g >= 0; --g) {
        int cnt = (g == 15) ? 31 : 32;
        float* K  = Kb  + buf * 32 * 260;
        float* Am = Asm + buf * 32 * 33;
        float* iv = ivs + buf * 32;

        // ---- b-phase: 8 warps x 4 rows, b_j = invn_j * (k_j . v)
        {
            float ve[8];
            #pragma unroll
            for (int e = 0; e < 8; e++) ve[e] = vsm[lane + 32 * e];
            #pragma unroll
            for (int jj = 0; jj < 4; jj++) {
                int j = w * 4 + jj;
                float s = 0.f;
                #pragma unroll
                for (int e = 0; e < 8; e++)
                    s += K[j * 260 + lane + 32 * e] * ve[e];
                #pragma unroll
                for (int o = 16; o > 0; o >>= 1)
                    s += __shfl_xor_sync(0xffffffff, s, o);
                if (lane == 0) bsm[j] = (j < cnt) ? s * iv[j] : 0.f;
            }
        }
        __syncthreads();

        // ---- solve (warp 0) || prefetch next chunk (warps 1..7)
        if (w == 0) {
            float ar[32];
            #pragma unroll
            for (int l = 0; l < 32; l++) ar[l] = Am[lane * 33 + l];
            float r = bsm[lane];
            float my_s = 0.f;
            #pragma unroll
            for (int l = 0; l < 32; l++) {
                float s = __shfl_sync(0xffffffff, r, l);
                if (lane == l) my_s = s;
                r -= ar[l] * s;
            }
            if (lane < cnt) {
                float cs = CEMA * my_s;
                csm[lane]  = cs;
                cnsm[lane] = cs * iv[lane];
            }
        } else if (g > 0) {
            int nb = buf ^ 1;
            float* Kn = Kb + nb * 32 * 260;
            int tHn = 32 * (g - 1) + 31;
            for (int idx = tid - 32; idx < 2048; idx += 224) {
                int j = idx >> 6, c4 = idx & 63;
                float4 v = *(const float4*)(Hb + (long)(tHn - j) * Hd + c4 * 4);
                *(float4*)(Kn + j * 260 + c4 * 4) = v;
            }
            float* An = Asm + nb * 32 * 33;
            const float* Ag = Ab + (g - 1) * 1024;
            for (int idx = tid - 32; idx < 1024; idx += 224)
                An[(idx >> 5) * 33 + (idx & 31)] = Ag[idx];
            if (tid - 32 < 32) ivs[nb * 32 + (tid - 32)] = In[tHn - (tid - 32)];
        }
        __syncthreads();

        // ---- rank-cnt update of v and m (all 256 threads, element tid)
        {
            float vi = vsm[tid];
            #pragma unroll 8
            for (int j = 0; j < cnt; j++) {
                float kj = K[j * 260 + tid];
                mi += csm[j] * kj;
                vi -= cnsm[j] * kj;
            }
            vsm[tid] = vi;
        }
        __syncthreads();
        buf ^= 1;
    }

    mout[bId * Hd + tid] = mi;
}

// ---------------------------------------------------------------------------
// mm = m @ Wrp + brp
// ---------------------------------------------------------------------------
__global__ __launch_bounds__(256) void rp_kernel(
    const float* __restrict__ m, const float* __restrict__ Wrp,
    const float* __restrict__ brp, float* __restrict__ mm)
{
    int b = blockIdx.x, c = threadIdx.x;
    __shared__ float ms[Hd];
    ms[c] = m[b * Hd + c];
    __syncthreads();
    float acc = brp[c];
    #pragma unroll 8
    for (int k = 0; k < Hd; k++) acc += ms[k] * Wrp[k * Hd + c];
    mm[b * Hd + c] = acc;
}

// ---------------------------------------------------------------------------
// out[8,32000] = mm @ Wout + bout
// ---------------------------------------------------------------------------
__global__ __launch_bounds__(128) void out_kernel(
    const float* __restrict__ mm, const float* __restrict__ Wout,
    const float* __restrict__ bout, float* __restrict__ out)
{
    __shared__ float ms[Bq][Hd];
    int tid = threadIdx.x;
    #pragma unroll
    for (int i = tid; i < Bq * Hd; i += 128) ms[i >> 8][i & 255] = mm[i];
    __syncthreads();

    int col = blockIdx.x * 128 + tid;
    float acc[Bq];
    float bo = bout[col];
    #pragma unroll
    for (int b = 0; b < Bq; b++) acc[b] = bo;

    #pragma unroll 4
    for (int k = 0; k < Hd; k++) {
        float w = Wout[(long)k * Vv + col];
        #pragma unroll
        for (int b = 0; b < Bq; b++) acc[b] += ms[b][k] * w;
    }
    #pragma unroll
    for (int b = 0; b < Bq; b++) out[(long)b * Vv + col] = acc[b];
}

// ---------------------------------------------------------------------------
extern "C" void kernel_launch(void* const* d_in, const int* in_sizes, int n_in,
                              void* d_out, int out_size)
{
    const int*   seq   = (const int*)  d_in[0];
    const float* embed = (const float*)d_in[1];
    const float* W1    = (const float*)d_in[2];
    const float* b1    = (const float*)d_in[3];
    const float* W2    = (const float*)d_in[4];
    const float* b2    = (const float*)d_in[5];
    const float* gamma = (const float*)d_in[6];
    const float* beta  = (const float*)d_in[7];
    const float* Wrp   = (const float*)d_in[8];
    const float* brp   = (const float*)d_in[9];
    const float* Wout  = (const float*)d_in[10];
    const float* bout  = (const float*)d_in[11];
    float* out = (float*)d_out;

    float *t1, *x, *he, *invn, *Am, *m, *mm;
    cudaGetSymbolAddress((void**)&t1,   g_t1);
    cudaGetSymbolAddress((void**)&x,    g_x);
    cudaGetSymbolAddress((void**)&he,   g_he);
    cudaGetSymbolAddress((void**)&invn, g_in);
    cudaGetSymbolAddress((void**)&Am,   g_A);
    cudaGetSymbolAddress((void**)&m,    g_m);
    cudaGetSymbolAddress((void**)&mm,   g_mm);

    // opt-in smem sizes (idempotent)
    static_assert((2*32*260 + 2*32*33 + 256 + 32*3 + 64) * 4 == 76672, "");
    cudaFuncSetAttribute(scan_kernel,
        cudaFuncAttributeMaxDynamicSharedMemorySize, 76672);
    cudaFuncSetAttribute(gram_kernel,
        cudaFuncAttributeMaxDynamicSharedMemorySize, 49408);

    // 1) t1 = relu(embed[seq] @ W1 + b1)
    sgemm_kernel<true, true, false><<<dim3(512 / 64, 4096 / 64), 256>>>(
        nullptr, W1, b1, t1, NTOK, 512, Hd, seq, embed);

    // 2) x = t1 @ W2 + b2 + embed[seq]
    sgemm_kernel<false, false, true><<<dim3(Hd / 64, 4096 / 64), 256>>>(
        t1, W2, b2, x, NTOK, Hd, 512, seq, embed);

    // 3) LayerNorm + row norms
    ln_kernel<<<NTOK / 8, 256>>>(x, gamma, beta, he, invn);

    // 4a) per-chunk scaled Gram matrices (parallel, 128 blocks)
    gram_kernel<<<Bq * NCH, 256, 49408>>>(he, invn, Am);

    // 4b) chunked sequential scan -> m
    scan_kernel<<<Bq, 256, 76672>>>(he, invn, Am, m);

    // 5) mm = m @ Wrp + brp
    rp_kernel<<<Bq, Hd>>>(m, Wrp, brp, mm);

    // 6) out = mm @ Wout + bout
    out_kernel<<<Vv / 128, 128>>>(mm, Wout, bout, out);
}

// round 3
// speedup vs baseline: 1.6673x; 1.2472x over previous
#include <cuda_runtime.h>
#include <cuda_bf16.h>

// Problem constants
#define Hd   256
#define Ld   512
#define Bq   8
#define NTOK 4096            // B*L
#define Vv   32000
#define CEMA 0.05f           // 1 - alpha
#define NCH  16              // chunks per batch
#define KSTR 264             // K tile smem row stride (8*33 -> conflict-free)

// Scratch (device globals)
__device__ float g_t1[NTOK * 512];
__device__ float g_x [NTOK * Hd];
__device__ float g_he[NTOK * Hd];
__device__ float g_in[NTOK];
__device__ float g_T [Bq * NCH * 32 * 32];  // per-chunk (I+L)^-1
__device__ float g_m [Bq * Hd];
__device__ float g_mm[Bq * Hd];

// cp.async helpers
__device__ __forceinline__ void cp16(void* dst, const void* src) {
    unsigned d = (unsigned)__cvta_generic_to_shared(dst);
    asm volatile("cp.async.ca.shared.global [%0], [%1], 16;\n" :: "r"(d), "l"(src));
}
#define CP_COMMIT() asm volatile("cp.async.commit_group;\n" ::: "memory")
#define CP_WAIT0()  asm volatile("cp.async.wait_group 0;\n" ::: "memory")

// ---------------------------------------------------------------------------
// Tiled SGEMM (unchanged)
// ---------------------------------------------------------------------------
template<bool GATHER, bool RELU, bool RESID>
__global__ __launch_bounds__(256) void sgemm_kernel(
    const float* __restrict__ A, const float* __restrict__ Bm,
    const float* __restrict__ bias, float* __restrict__ C,
    int M, int N, int K,
    const int* __restrict__ seq, const float* __restrict__ embed)
{
    constexpr int BM = 64, BN = 64, BK = 16, TM = 4, TN = 4;
    __shared__ float As[BK][BM];
    __shared__ float Bs[BK][BN];

    const int tid = threadIdx.x;
    const int tx = tid % (BN / TN);
    const int ty = tid / (BN / TN);
    const int rowBase = blockIdx.y * BM;
    const int colBase = blockIdx.x * BN;

    float acc[TM][TN];
    #pragma unroll
    for (int i = 0; i < TM; i++)
        #pragma unroll
        for (int j = 0; j < TN; j++) acc[i][j] = 0.f;

    for (int k0 = 0; k0 < K; k0 += BK) {
        #pragma unroll
        for (int i = tid; i < BM * BK; i += 256) {
            int m = i / BK, kk = i % BK;
            int gr = rowBase + m;
            const float* arow = GATHER ? (embed + (long)seq[gr] * K)
                                       : (A + (long)gr * K);
            As[kk][m] = arow[k0 + kk];
        }
        #pragma unroll
        for (int i = tid; i < BK * BN; i += 256) {
            int kk = i / BN, n = i % BN;
            Bs[kk][n] = Bm[(long)(k0 + kk) * N + colBase + n];
        }
        __syncthreads();

        #pragma unroll
        for (int kk = 0; kk < BK; kk++) {
            float af[TM], bf[TN];
            #pragma unroll
            for (int i = 0; i < TM; i++) af[i] = As[kk][ty * TM + i];
            #pragma unroll
            for (int j = 0; j < TN; j++) bf[j] = Bs[kk][tx * TN + j];
            #pragma unroll
            for (int i = 0; i < TM; i++)
                #pragma unroll
                for (int j = 0; j < TN; j++) acc[i][j] += af[i] * bf[j];
        }
        __syncthreads();
    }

    #pragma unroll
    for (int i = 0; i < TM; i++) {
        int r = rowBase + ty * TM + i;
        const float* erow = RESID ? (embed + (long)seq[r] * N) : nullptr;
        #pragma unroll
        for (int j = 0; j < TN; j++) {
            int c = colBase + tx * TN + j;
            float v = acc[i][j] + bias[c];
            if (RELU)  v = fmaxf(v, 0.f);
            if (RESID) v += erow[c];
            C[(long)r * N + c] = v;
        }
    }
}

// ---------------------------------------------------------------------------
// LayerNorm + row norm (unchanged)
// ---------------------------------------------------------------------------
__global__ __launch_bounds__(256) void ln_kernel(
    const float* __restrict__ X, const float* __restrict__ g,
    const float* __restrict__ b, float* __restrict__ Y,
    float* __restrict__ invn)
{
    int row  = blockIdx.x * 8 + (threadIdx.x >> 5);
    int lane = threadIdx.x & 31;
    const float* x = X + (long)row * Hd;

    float v[8];
    float s = 0.f;
    #pragma unroll
    for (int j = 0; j < 8; j++) { v[j] = x[lane + 32 * j]; s += v[j]; }
    #pragma unroll
    for (int o = 16; o > 0; o >>= 1) s += __shfl_xor_sync(0xffffffff, s, o);
    float mu = s * (1.f / Hd);

    float ss = 0.f;
    #pragma unroll
    for (int j = 0; j < 8; j++) { float d = v[j] - mu; ss += d * d; }
    #pragma unroll
    for (int o = 16; o > 0; o >>= 1) ss += __shfl_xor_sync(0xffffffff, ss, o);
    float rstd = rsqrtf(ss * (1.f / Hd) + 1e-5f);

    float ns = 0.f;
    #pragma unroll
    for (int j = 0; j < 8; j++) {
        int c = lane + 32 * j;
        float o = (v[j] - mu) * rstd * g[c] + b[c];
        Y[(long)row * Hd + c] = o;
        ns += o * o;
    }
    #pragma unroll
    for (int o = 16; o > 0; o >>= 1) ns += __shfl_xor_sync(0xffffffff, ns, o);

    if (lane == 0) invn[row] = 1.f / fmaxf(sqrtf(ns), 1e-12f);
}

// ---------------------------------------------------------------------------
// Prep kernel: per chunk, compute scaled Gram L then T = (I + strict_lower(L))^-1.
// 128 blocks (8 batches x 16 chunks), 256 threads.
// ---------------------------------------------------------------------------
__global__ __launch_bounds__(256) void prep_kernel(
    const float* __restrict__ He, const float* __restrict__ invn,
    float* __restrict__ Tout)
{
    extern __shared__ float sh[];
    float* Ks   = sh;                 // [32][257]
    float* part = Ks + 32 * 257;      // [4][32][32]
    float* iv   = part + 4 * 1024;    // [32]
    float* G    = iv + 32;            // [32][33]

    int bId = blockIdx.x >> 4;
    int g   = blockIdx.x & 15;
    int tid = threadIdx.x;
    int tHi = min(32 * g + 31, 510);
    const float* Hb = He + (long)bId * Ld * Hd;

    for (int idx = tid; idx < 32 * 256; idx += 256) {
        int j = idx >> 8, c = idx & 255;
        Ks[j * 257 + c] = Hb[(long)(tHi - j) * Hd + c];
    }
    if (tid < 32) iv[tid] = invn[bId * Ld + tHi - tid];
    __syncthreads();

    int grp = tid >> 6;
    int t64 = tid & 63;
    int tx  = t64 & 7, ty = t64 >> 3;
    int k0  = grp * 64;

    float acc[4][4];
    #pragma unroll
    for (int i = 0; i < 4; i++)
        #pragma unroll
        for (int j = 0; j < 4; j++) acc[i][j] = 0.f;

    #pragma unroll 4
    for (int kk = 0; kk < 64; kk++) {
        float av[4], bv[4];
        #pragma unroll
        for (int i = 0; i < 4; i++) av[i] = Ks[(ty * 4 + i) * 257 + k0 + kk];
        #pragma unroll
        for (int i = 0; i < 4; i++) bv[i] = Ks[(tx * 4 + i) * 257 + k0 + kk];
        #pragma unroll
        for (int i = 0; i < 4; i++)
            #pragma unroll
            for (int j = 0; j < 4; j++) acc[i][j] += av[i] * bv[j];
    }

    #pragma unroll
    for (int i = 0; i < 4; i++)
        #pragma unroll
        for (int j = 0; j < 4; j++)
            part[grp * 1024 + (ty * 4 + i) * 32 + tx * 4 + j] = acc[i][j];
    __syncthreads();

    // reduce partitions -> scaled Gram G[j][l]
    for (int e = tid; e < 1024; e += 256) {
        int j = e >> 5, l = e & 31;
        float s = part[e] + part[1024 + e] + part[2048 + e] + part[3072 + e];
        G[j * 33 + l] = CEMA * iv[j] * iv[l] * s;
    }
    __syncthreads();

    // warp 0: T = (I + strict_lower(G))^-1 by per-column forward substitution.
    // Lane c owns column c; x_j = delta_jc - sum_{l<j} G[j][l] * x_l.
    if (tid < 32) {
        int c = tid;
        float x[32];
        #pragma unroll
        for (int j = 0; j < 32; j++) {
            float sum = (j == c) ? 1.f : 0.f;
            #pragma unroll
            for (int l = 0; l < 32; l++) {
                if (l < j) sum -= G[j * 33 + l] * x[l];
            }
            x[j] = sum;
        }
        float* Tg = Tout + ((long)(bId * NCH + g) << 10);
        #pragma unroll
        for (int j = 0; j < 32; j++)
            Tg[j * 32 + c] = x[j];
    }
}

// ---------------------------------------------------------------------------
// Chunked backward delta-rule scan v3: no sequential solve.
// Per chunk: b = iv .* (K v)  ->  s = T b  ->  v -= Kt(c s iv), m += Kt(c s)
// cp.async double-buffered K tile / T / iv.
// ---------------------------------------------------------------------------
__global__ __launch_bounds__(256) void scan_kernel(
    const float* __restrict__ He, const float* __restrict__ invn,
    const float* __restrict__ Tin, float* __restrict__ mout)
{
    extern __shared__ float sh[];
    float* Kb   = sh;                    // [2][32][KSTR]
    float* Tb   = Kb + 2 * 32 * KSTR;    // [2][1024]
    float* ivb  = Tb + 2048;             // [2][32]
    float* vsm  = ivb + 64;              // [256]
    float* bsm  = vsm + 256;             // [32]
    float* csm  = bsm + 32;              // [32]
    float* cnsm = csm + 32;              // [32]

    int bId = blockIdx.x;
    int tid = threadIdx.x;
    const float* Hb = He + (long)bId * Ld * Hd;
    const float* In = invn + bId * Ld;
    const float* Tc = Tin + ((long)bId * NCH << 10);

    // ---- async load of chunk g into buffer buf
    auto issue = [&](int buf, int g) {
        int tHi = (g == 15) ? 510 : (32 * g + 31);
        float* K = Kb + buf * 32 * KSTR;
        #pragma unroll
        for (int r = 0; r < 8; r++) {
            int idx = tid + 256 * r;
            int j = idx >> 6, c4 = idx & 63;
            cp16(K + j * KSTR + c4 * 4,
                 Hb + (long)(tHi - j) * Hd + c4 * 4);
        }
        cp16(Tb + buf * 1024 + tid * 4, Tc + (g << 10) + tid * 4);
        if (tid < 32) ivb[buf * 32 + tid] = In[tHi - tid];  // plain (reversed)
    };

    // prologue
    issue(0, 15);
    CP_COMMIT();
    vsm[tid] = Hb[511 * Hd + tid];   // v = q
    float mi = 0.f;
    CP_WAIT0();
    __syncthreads();

    int jrow = tid >> 3, sub = tid & 7;
    int buf = 0;
    for (int g = 15; g >= 0; --g) {
        if (g > 0) { issue(buf ^ 1, g - 1); CP_COMMIT(); }

        float* K  = Kb + buf * 32 * KSTR;
        float* T  = Tb + buf * 1024;
        float* iv = ivb + buf * 32;

        // ---- phase A: b_j = iv_j * (k_j . v), 8 lanes per row
        {
            const float* Kr = K + jrow * KSTR;
            float s = 0.f;
            #pragma unroll
            for (int i = 0; i < 32; i++)
                s += Kr[sub + 8 * i] * vsm[sub + 8 * i];
            s += __shfl_xor_sync(0xffffffff, s, 1);
            s += __shfl_xor_sync(0xffffffff, s, 2);
            s += __shfl_xor_sync(0xffffffff, s, 4);
            if (sub == 0) bsm[jrow] = s * iv[jrow];
        }
        __syncthreads();

        // ---- phase B: s_j = sum_l T[j][l] b_l  (parallel matvec)
        {
            float t = 0.f;
            #pragma unroll
            for (int q = 0; q < 4; q++)
                t += T[jrow * 32 + sub * 4 + q] * bsm[sub * 4 + q];
            t += __shfl_xor_sync(0xffffffff, t, 1);
            t += __shfl_xor_sync(0xffffffff, t, 2);
            t += __shfl_xor_sync(0xffffffff, t, 4);
            if (sub == 0) {
                bool ok = (g < 15) || (jrow < 31);
                float sv = ok ? t : 0.f;
                float cs = CEMA * sv;
                csm[jrow]  = cs;
                cnsm[jrow] = cs * iv[jrow];
            }
        }
        __syncthreads();

        // ---- phase C: rank-32 update, element tid
        {
            float vi = vsm[tid];
            #pragma unroll
            for (int j = 0; j < 32; j++) {
                float kj = K[j * KSTR + tid];
                mi += csm[j] * kj;
                vi -= cnsm[j] * kj;
            }
            vsm[tid] = vi;
        }
        CP_WAIT0();
        __syncthreads();
        buf ^= 1;
    }

    mout[bId * Hd + tid] = mi;
}

// ---------------------------------------------------------------------------
// mm = m @ Wrp + brp
// ---------------------------------------------------------------------------
__global__ __launch_bounds__(256) void rp_kernel(
    const float* __restrict__ m, const float* __restrict__ Wrp,
    const float* __restrict__ brp, float* __restrict__ mm)
{
    int b = blockIdx.x, c = threadIdx.x;
    __shared__ float ms[Hd];
    ms[c] = m[b * Hd + c];
    __syncthreads();
    float acc = brp[c];
    #pragma unroll 8
    for (int k = 0; k < Hd; k++) acc += ms[k] * Wrp[k * Hd + c];
    mm[b * Hd + c] = acc;
}

// ---------------------------------------------------------------------------
// out[8,32000] = mm @ Wout + bout
// ---------------------------------------------------------------------------
__global__ __launch_bounds__(128) void out_kernel(
    const float* __restrict__ mm, const float* __restrict__ Wout,
    const float* __restrict__ bout, float* __restrict__ out)
{
    __shared__ float ms[Bq][Hd];
    int tid = threadIdx.x;
    #pragma unroll
    for (int i = tid; i < Bq * Hd; i += 128) ms[i >> 8][i & 255] = mm[i];
    __syncthreads();

    int col = blockIdx.x * 128 + tid;
    float acc[Bq];
    float bo = bout[col];
    #pragma unroll
    for (int b = 0; b < Bq; b++) acc[b] = bo;

    #pragma unroll 4
    for (int k = 0; k < Hd; k++) {
        float w = Wout[(long)k * Vv + col];
        #pragma unroll
        for (int b = 0; b < Bq; b++) acc[b] += ms[b][k] * w;
    }
    #pragma unroll
    for (int b = 0; b < Bq; b++) out[(long)b * Vv + col] = acc[b];
}

// ---------------------------------------------------------------------------
extern "C" void kernel_launch(void* const* d_in, const int* in_sizes, int n_in,
                              void* d_out, int out_size)
{
    const int*   seq   = (const int*)  d_in[0];
    const float* embed = (const float*)d_in[1];
    const float* W1    = (const float*)d_in[2];
    const float* b1    = (const float*)d_in[3];
    const float* W2    = (const float*)d_in[4];
    const float* b2    = (const float*)d_in[5];
    const float* gamma = (const float*)d_in[6];
    const float* beta  = (const float*)d_in[7];
    const float* Wrp   = (const float*)d_in[8];
    const float* brp   = (const float*)d_in[9];
    const float* Wout  = (const float*)d_in[10];
    const float* bout  = (const float*)d_in[11];
    float* out = (float*)d_out;

    float *t1, *x, *he, *invn, *Tm, *m, *mm;
    cudaGetSymbolAddress((void**)&t1,   g_t1);
    cudaGetSymbolAddress((void**)&x,    g_x);
    cudaGetSymbolAddress((void**)&he,   g_he);
    cudaGetSymbolAddress((void**)&invn, g_in);
    cudaGetSymbolAddress((void**)&Tm,   g_T);
    cudaGetSymbolAddress((void**)&m,    g_m);
    cudaGetSymbolAddress((void**)&mm,   g_mm);

    // smem sizes
    const int prepSmem = (32 * 257 + 4 * 1024 + 32 + 32 * 33) * 4;   // 53632
    const int scanSmem = (2 * 32 * KSTR + 2048 + 64 + 256 + 96) * 4; // 77440
    cudaFuncSetAttribute(prep_kernel,
        cudaFuncAttributeMaxDynamicSharedMemorySize, prepSmem);
    cudaFuncSetAttribute(scan_kernel,
        cudaFuncAttributeMaxDynamicSharedMemorySize, scanSmem);

    // 1) t1 = relu(embed[seq] @ W1 + b1)
    sgemm_kernel<true, true, false><<<dim3(512 / 64, 4096 / 64), 256>>>(
        nullptr, W1, b1, t1, NTOK, 512, Hd, seq, embed);

    // 2) x = t1 @ W2 + b2 + embed[seq]
    sgemm_kernel<false, false, true><<<dim3(Hd / 64, 4096 / 64), 256>>>(
        t1, W2, b2, x, NTOK, Hd, 512, seq, embed);

    // 3) LayerNorm + row norms
    ln_kernel<<<NTOK / 8, 256>>>(x, gamma, beta, he, invn);

    // 4a) per-chunk T = (I+L)^-1 (parallel, 128 blocks)
    prep_kernel<<<Bq * NCH, 256, prepSmem>>>(he, invn, Tm);

    // 4b) chunked sequential scan -> m (no sequential solve inside)
    scan_kernel<<<Bq, 256, scanSmem>>>(he, invn, Tm, m);

    // 5) mm = m @ Wrp + brp
    rp_kernel<<<Bq, Hd>>>(m, Wrp, brp, mm);

    // 6) out = mm @ Wout + bout
    out_kernel<<<Vv / 128, 128>>>(mm, Wout, bout, out);
}